// round 4
// baseline (speedup 1.0000x reference)
#include <cuda_runtime.h>
#include <math.h>

// Shape fixed by reference: B=2, L=2048, H=16, E=64
#define B_  2
#define L_  2048
#define H_  16
#define E_  64
#define BH_ 32            // B*H chains
#define CH_ 64            // chunk length along s
#define NC_ 32            // chunks per chain
#define HE_ 1024          // H*E row stride in floats
#define NBLK (BH_ * NC_)  // 1024 blocks
#define NSUB 4
#define RPS  16           // rows per sub

// Scratch (__device__ globals; no allocations allowed)
__device__ float g_agg [NBLK * E_];  // per-chunk sum of e*V
__device__ float g_aggE[NBLK];       // per-chunk sum of e
__device__ int   g_flag[NBLK];       // publish flags

__global__ void reset_flags() { g_flag[threadIdx.x] = 0; }

__device__ __forceinline__ void st_release_gpu(int* p, int v) {
    asm volatile("st.release.gpu.global.b32 [%0], %1;" :: "l"(p), "r"(v) : "memory");
}
__device__ __forceinline__ int ld_acquire_gpu(const int* p) {
    int v;
    asm volatile("ld.acquire.gpu.global.b32 %0, [%1];" : "=r"(v) : "l"(p) : "memory");
    return v;
}

__global__ __launch_bounds__(256, 7) void fused_scan_attn(
    const float* __restrict__ keys,
    const float* __restrict__ values,
    const float* __restrict__ w_score,
    float* __restrict__ out)
{
    __shared__ float sV[CH_ * E_];     // 16 KB V tile
    __shared__ float se[CH_];          // e-scores for this chunk
    __shared__ float spEV[NSUB * E_];  // per-sub partial sums of e*V
    __shared__ float spE[NSUB];
    __shared__ float sqEV[NSUB * E_];  // cross-block partial prefix (per sub)
    __shared__ float sqE[NSUB];

    const int tid = threadIdx.x;
    const int blk = blockIdx.x;
    const int bh  = blk >> 5;          // / NC_
    const int c   = blk & 31;          // % NC_
    const int b   = bh >> 4;
    const int h   = bh & 15;
    const int base = ((b * L_ + c * CH_) * H_ + h) * E_;

    const int d   = tid & 63;          // channel
    const int sub = tid >> 6;          // sub-group 0..3
    const int r0  = sub * RPS;

    // ---- phase 1: e[row] = exp(0.125 * dot(K[row], w_k)); 4 threads per row
    {
        const int row = tid >> 2, q = tid & 3;
        const float4* kq = reinterpret_cast<const float4*>(
            keys + base + row * HE_ + q * 16);
        const float4* wq = reinterpret_cast<const float4*>(
            w_score + E_ + q * 16);
        float dot = 0.f;
        #pragma unroll
        for (int j = 0; j < 4; j++) {
            const float4 k4 = kq[j];
            const float4 w4 = wq[j];
            dot += k4.x * w4.x + k4.y * w4.y + k4.z * w4.z + k4.w * w4.w;
        }
        dot += __shfl_xor_sync(0xffffffffu, dot, 1);
        dot += __shfl_xor_sync(0xffffffffu, dot, 2);
        if (q == 0) se[row] = __expf(dot * 0.125f);
    }

    // ---- phase 2: stage V tile into smem (float4, coalesced)
    {
        const float4* vg = reinterpret_cast<const float4*>(values + base);
        float4* sv4 = reinterpret_cast<float4*>(sV);
        #pragma unroll
        for (int i = 0; i < 4; i++) {
            const int idx = tid + i * 256;       // float4 index 0..1023
            const int rr = idx >> 4, d4 = idx & 15;
            sv4[idx] = vg[rr * (HE_ / 4) + d4];
        }
    }
    __syncthreads();

    // ---- phase 3: per-sub partial aggregates over 16 rows
    {
        float sumE = 0.f, sumEV = 0.f;
        #pragma unroll
        for (int r = 0; r < RPS; r++) {
            const float e = se[r0 + r];
            sumE += e;
            sumEV = fmaf(e, sV[(r0 + r) * E_ + d], sumEV);
        }
        spEV[sub * E_ + d] = sumEV;
        if (d == 0) spE[sub] = sumE;
    }
    __syncthreads();

    // combine sub partials -> block aggregate
    if (tid < E_) {
        g_agg[blk * E_ + tid] =
            spEV[tid] + spEV[E_ + tid] + spEV[2 * E_ + tid] + spEV[3 * E_ + tid];
        if (tid == 0)
            g_aggE[blk] = spE[0] + spE[1] + spE[2] + spE[3];
    }
    __syncthreads();
    // publish: cumulative release orders the block's aggregate stores
    if (tid == 0) st_release_gpu(&g_flag[blk], 1);

    // ---- lookback wait: one warp, acquire loads, ballot exit
    if (tid < 32) {
        bool done = (tid >= c);
        while (!__all_sync(0xffffffffu, done)) {
            if (!done) done = (ld_acquire_gpu(&g_flag[bh * NC_ + tid]) != 0);
        }
    }
    __syncthreads();

    // ---- phase 4a: cross-block exclusive prefix, split across subs
    {
        float pEV = 0.f;
        for (int t = sub; t < c; t += NSUB)
            pEV += g_agg[(bh * NC_ + t) * E_ + d];
        sqEV[sub * E_ + d] = pEV;
        if (d == 0) {
            float pE = 0.f;
            for (int t = sub; t < c; t += NSUB)
                pE += g_aggE[bh * NC_ + t];
            sqE[sub] = pE;
        }
    }
    __syncthreads();

    // ---- phase 4b: per-thread exclusive start + in-sub inclusive scan
    {
        float accEV = sqEV[d] + sqEV[E_ + d] + sqEV[2 * E_ + d] + sqEV[3 * E_ + d];
        float accE  = sqE[0] + sqE[1] + sqE[2] + sqE[3];
        #pragma unroll
        for (int s = 0; s < NSUB - 1; s++) {
            if (s < sub) {
                accEV += spEV[s * E_ + d];
                accE  += spE[s];
            }
        }
        float* o = out + base + r0 * HE_ + d;
        #pragma unroll
        for (int r = 0; r < RPS; r++) {
            const float e = se[r0 + r];
            accE += e;
            accEV = fmaf(e, sV[(r0 + r) * E_ + d], accEV);
            __stcs(o + r * HE_, __fdividef(accEV, accE));  // streaming store
        }
    }
}

extern "C" void kernel_launch(void* const* d_in, const int* in_sizes, int n_in,
                              void* d_out, int out_size) {
    // inputs: 0=queries (unused: a_q cancels in softmax), 1=keys, 2=values,
    //         3=w_score, 4=b_score (unused: cancels)
    const float* keys   = (const float*)d_in[1];
    const float* values = (const float*)d_in[2];
    const float* w      = (const float*)d_in[3];
    float* out = (float*)d_out;

    reset_flags<<<1, NBLK>>>();
    fused_scan_attn<<<NBLK, 256>>>(keys, values, w, out);
}

// round 5
// speedup vs baseline: 1.3743x; 1.3743x over previous
#include <cuda_runtime.h>
#include <math.h>

// Shape fixed by reference: B=2, L=2048, H=16, E=64
#define B_  2
#define L_  2048
#define H_  16
#define E_  64
#define BH_ 32            // B*H chains
#define CH_ 128           // chunk length along s
#define NC_ 16            // chunks per chain
#define HE_ 1024          // H*E row stride in floats
#define NBLK (BH_ * NC_)  // 512 blocks
#define NT_  512          // threads per block
#define NSUB 8            // sub-groups of 64 channels
#define RPS  16           // rows per sub

// Scratch (__device__ globals; no allocations allowed)
__device__ float g_agg [NBLK * E_];  // per-chunk sum of e*V
__device__ float g_aggE[NBLK];       // per-chunk sum of e
__device__ int   g_flag[NBLK];       // publish flags

__global__ void reset_flags() { g_flag[threadIdx.x] = 0; }

__global__ __launch_bounds__(NT_, 4) void fused_scan_attn(
    const float* __restrict__ keys,
    const float* __restrict__ values,
    const float* __restrict__ w_score,
    float* __restrict__ out)
{
    __shared__ float sV[CH_ * E_];     // 32 KB V tile
    __shared__ float se[CH_];          // e-scores for this chunk
    __shared__ float spEV[NSUB * E_];  // per-sub partial sums of e*V
    __shared__ float spE[NSUB];
    __shared__ float sqEV[NSUB * E_];  // cross-block partial prefix (per sub)
    __shared__ float sqE[NSUB];

    const int tid = threadIdx.x;
    const int blk = blockIdx.x;
    const int bh  = blk >> 4;          // / NC_
    const int c   = blk & 15;          // % NC_
    const int b   = bh >> 4;           // / H_
    const int h   = bh & 15;           // % H_
    const int base = ((b * L_ + c * CH_) * H_ + h) * E_;

    const int d   = tid & 63;          // channel
    const int sub = tid >> 6;          // sub-group 0..7
    const int r0  = sub * RPS;

    // ---- phase 1: e[row] = exp(0.125 * dot(K[row], w_k)); 4 threads per row
    {
        const int row = tid >> 2, q = tid & 3;
        const float4* kq = reinterpret_cast<const float4*>(
            keys + base + row * HE_ + q * 16);
        const float4* wq = reinterpret_cast<const float4*>(
            w_score + E_ + q * 16);
        float dot = 0.f;
        #pragma unroll
        for (int j = 0; j < 4; j++) {
            const float4 k4 = kq[j];
            const float4 w4 = wq[j];
            dot += k4.x * w4.x + k4.y * w4.y + k4.z * w4.z + k4.w * w4.w;
        }
        dot += __shfl_xor_sync(0xffffffffu, dot, 1);
        dot += __shfl_xor_sync(0xffffffffu, dot, 2);
        if (q == 0) se[row] = __expf(dot * 0.125f);
    }

    // ---- phase 2: stage V tile into smem (float4, coalesced)
    {
        const float4* vg = reinterpret_cast<const float4*>(values + base);
        float4* sv4 = reinterpret_cast<float4*>(sV);
        #pragma unroll
        for (int i = 0; i < 4; i++) {
            const int idx = tid + i * NT_;       // float4 index 0..2047
            const int rr = idx >> 4, d4 = idx & 15;
            sv4[idx] = vg[rr * (HE_ / 4) + d4];
        }
    }
    __syncthreads();

    // ---- phase 3: per-sub partial aggregates over 16 rows
    {
        float sumE = 0.f, sumEV = 0.f;
        #pragma unroll
        for (int r = 0; r < RPS; r++) {
            const float e = se[r0 + r];
            sumE += e;
            sumEV = fmaf(e, sV[(r0 + r) * E_ + d], sumEV);
        }
        spEV[sub * E_ + d] = sumEV;
        if (d == 0) spE[sub] = sumE;
    }
    __syncthreads();

    // combine sub partials -> block aggregate, publish (R2-style mechanics)
    if (tid < E_) {
        float a = 0.f;
        #pragma unroll
        for (int s = 0; s < NSUB; s++) a += spEV[s * E_ + tid];
        g_agg[blk * E_ + tid] = a;
        if (tid == 0) {
            float ae = 0.f;
            #pragma unroll
            for (int s = 0; s < NSUB; s++) ae += spE[s];
            g_aggE[blk] = ae;
        }
        __threadfence();                 // order agg stores before flag
    }
    __syncthreads();
    if (tid == 0) atomicExch(&g_flag[blk], 1);

    // ---- lookback: wait for ALL predecessors in this chain (<=15)
    if (tid < c) {
        while (atomicAdd(&g_flag[bh * NC_ + tid], 0) == 0) { }
        __threadfence();                 // acquire predecessors' agg stores
    }
    __syncthreads();

    // ---- phase 4a: cross-block exclusive prefix, split across 8 subs
    {
        float pEV = 0.f;
        for (int t = sub; t < c; t += NSUB)
            pEV += g_agg[(bh * NC_ + t) * E_ + d];
        sqEV[sub * E_ + d] = pEV;
        if (d == 0) {
            float pE = 0.f;
            for (int t = sub; t < c; t += NSUB)
                pE += g_aggE[bh * NC_ + t];
            sqE[sub] = pE;
        }
    }
    __syncthreads();

    // ---- phase 4b: exclusive start + in-sub inclusive scan + output
    {
        float accEV = 0.f, accE = 0.f;
        #pragma unroll
        for (int s = 0; s < NSUB; s++) {
            accEV += sqEV[s * E_ + d];
            accE  += sqE[s];
        }
        #pragma unroll
        for (int s = 0; s < NSUB - 1; s++) {
            if (s < sub) {
                accEV += spEV[s * E_ + d];
                accE  += spE[s];
            }
        }
        float* o = out + base + r0 * HE_ + d;
        #pragma unroll
        for (int r = 0; r < RPS; r++) {
            const float e = se[r0 + r];
            accE += e;
            accEV = fmaf(e, sV[(r0 + r) * E_ + d], accEV);
            o[r * HE_] = __fdividef(accEV, accE);
        }
    }
}

extern "C" void kernel_launch(void* const* d_in, const int* in_sizes, int n_in,
                              void* d_out, int out_size) {
    // inputs: 0=queries (unused: a_q cancels in softmax), 1=keys, 2=values,
    //         3=w_score, 4=b_score (unused: cancels)
    const float* keys   = (const float*)d_in[1];
    const float* values = (const float*)d_in[2];
    const float* w      = (const float*)d_in[3];
    float* out = (float*)d_out;

    reset_flags<<<1, NBLK>>>();
    fused_scan_attn<<<NBLK, NT_>>>(keys, values, w, out);
}